// round 17
// baseline (speedup 1.0000x reference)
#include <cuda_runtime.h>

// Net_2095944040841: 3-layer LSTM (reference's buggy c-state wiring) on GB300.
// R16: 13 gate warps (3.25/SMSP), lane = (qd|bp|u). Strides kept at 76/108
// (u*stride mod 32 = {0,12,24,4}: conflict-free 8-lane LDS phases, the property
// that made R10 fast). Quarter overruns read zero INPUT columns -> products 0.
// 2-round shfl combine. R13 pipeline (2 barriers/step, helper x-load early).

#define T_LEN 1024
#define IN_D  20
#define HIDN  50
#define OUT_D 8
#define NB    4
#define NCTA  128
#define NTH   448

// shared memory layout (float offsets)
#define WA_STR 76            // cell1 row: 20 fused-x + 52 h1 + 4 pad
#define WB_STR 108           // cells2/3 row: 52 + 52 + 4 pad
#define WA_OFF 0             // 200 x 76   -> 15200
#define WB_OFF 15200         // 200 x 108  -> 36800
#define WC_OFF 36800         // 150 x 108  -> 53000
#define W2_OFF 53000         // 8 x 50     -> 53400
#define XH1_OFF 53400        // 2 x 320: [x 10 pairs | h1 30 pairs(52+pad)] -> 54040
#define C2_OFF  54040        // 4 slots x 224: [h1[0]|h2a[1]|h1[1]|h2a[0]] -> 54936
#define C3_OFF  54936        // 4 slots x 224: [h2b[0]|h3[1]|h2b[1]|h3[0]] -> 55832
#define SMEM_FLT 55832       // 223,328 bytes

typedef unsigned long long ull;

static __device__ __forceinline__ void upk(ull v, float &a, float &b) {
    asm("mov.b64 {%0,%1}, %2;" : "=f"(a), "=f"(b) : "l"(v));
}
static __device__ __forceinline__ ull fma2(ull a, ull b, ull c) {
    ull d; asm("fma.rn.f32x2 %0, %1, %2, %3;" : "=l"(d) : "l"(a), "l"(b), "l"(c)); return d;
}
static __device__ __forceinline__ ull add2(ull a, ull b) {
    ull d; asm("add.rn.f32x2 %0, %1, %2;" : "=l"(d) : "l"(a), "l"(b)); return d;
}
static __device__ __forceinline__ float tanhap(float x) {
    float t; asm("tanh.approx.f32 %0, %1;" : "=f"(t) : "f"(x)); return t;
}
static __device__ __forceinline__ float sigm(float x) {
    return fmaf(tanhap(0.5f * x), 0.5f, 0.5f);
}

struct Acc8 { ull i0, i1, f0, f1, g0, g1, o0, o1; };

// Quarter-GEMV: NQ chunks (4 cols) of 4 (or 3) gate rows x 2 batches.
// All pointers compile-time-indexed (no runtime strides).
template<int NQ, bool HASF>
static __device__ __forceinline__ void gemv_q(
    const float* __restrict__ wi, const float* __restrict__ wf,
    const float* __restrict__ wg, const float* __restrict__ wo,
    const float* __restrict__ inp, Acc8 &A)
{
#pragma unroll
    for (int kk = 0; kk < NQ; kk++) {
        ulonglong2 qa = *reinterpret_cast<const ulonglong2*>(inp + 16 * kk);
        ulonglong2 qb = *reinterpret_cast<const ulonglong2*>(inp + 16 * kk + 8);
        ulonglong2 wI = *(reinterpret_cast<const ulonglong2*>(wi) + kk);
        ulonglong2 wG = *(reinterpret_cast<const ulonglong2*>(wg) + kk);
        ulonglong2 wO = *(reinterpret_cast<const ulonglong2*>(wo) + kk);
        A.i0 = fma2(wI.x, qa.x, A.i0); A.i1 = fma2(wI.x, qa.y, A.i1);
        A.i0 = fma2(wI.y, qb.x, A.i0); A.i1 = fma2(wI.y, qb.y, A.i1);
        A.g0 = fma2(wG.x, qa.x, A.g0); A.g1 = fma2(wG.x, qa.y, A.g1);
        A.g0 = fma2(wG.y, qb.x, A.g0); A.g1 = fma2(wG.y, qb.y, A.g1);
        A.o0 = fma2(wO.x, qa.x, A.o0); A.o1 = fma2(wO.x, qa.y, A.o1);
        A.o0 = fma2(wO.y, qb.x, A.o0); A.o1 = fma2(wO.y, qb.y, A.o1);
        if (HASF) {
            ulonglong2 wF = *(reinterpret_cast<const ulonglong2*>(wf) + kk);
            A.f0 = fma2(wF.x, qa.x, A.f0); A.f1 = fma2(wF.x, qa.y, A.f1);
            A.f0 = fma2(wF.y, qb.x, A.f0); A.f1 = fma2(wF.y, qb.y, A.f1);
        }
    }
}

// combine quarters across lane bits 3 (xor8) and 4 (xor16)
#define CMB(a) { ull _o = __shfl_xor_sync(0xffffffffu, a, 8);  a = add2(a, _o); \
                 _o = __shfl_xor_sync(0xffffffffu, a, 16);     a = add2(a, _o); }
#define CMB4(A) { CMB(A.i0) CMB(A.i1) CMB(A.f0) CMB(A.f1) CMB(A.g0) CMB(A.g1) CMB(A.o0) CMB(A.o1) }
#define CMB3(A) { CMB(A.i0) CMB(A.i1) CMB(A.g0) CMB(A.g1) CMB(A.o0) CMB(A.o1) }

extern __shared__ float sm[];

__global__ void __launch_bounds__(NTH, 1)
lstm_persist_kernel(const float* __restrict__ x,
                    const float* __restrict__ W1,   const float* __restrict__ b1,
                    const float* __restrict__ Wih1, const float* __restrict__ Whh1,
                    const float* __restrict__ bih1, const float* __restrict__ bhh1,
                    const float* __restrict__ Wih2, const float* __restrict__ Whh2,
                    const float* __restrict__ bih2, const float* __restrict__ bhh2,
                    const float* __restrict__ Wih3, const float* __restrict__ Whh3,
                    const float* __restrict__ bih3, const float* __restrict__ bhh3,
                    const float* __restrict__ W2,   const float* __restrict__ b2,
                    float* __restrict__ out)
{
    const int tid = threadIdx.x;
    const int b0  = blockIdx.x * NB;

    // ---------------- init: weights ----------------
    for (int i = tid; i < HIDN * IN_D; i += NTH) sm[WB_OFF + i] = W1[i];  // stage W1
    __syncthreads();

    // WA x-part: Wc[r][k] = sum_j Wih1[r][j] * W1[j][k]
    for (int i = tid; i < 200 * IN_D; i += NTH) {
        int r = i / IN_D, k = i % IN_D;
        float acc = 0.f;
#pragma unroll 10
        for (int j = 0; j < HIDN; j++)
            acc += Wih1[r * HIDN + j] * sm[WB_OFF + j * IN_D + k];
        sm[WA_OFF + r * WA_STR + k] = acc;
    }
    // WA cols 20..75: 50 Whh1 + 6 zeros
    for (int i = tid; i < 200 * 56; i += NTH) {
        int r = i / 56, c = i % 56;
        sm[WA_OFF + r * WA_STR + IN_D + c] = (c < HIDN) ? Whh1[r * HIDN + c] : 0.f;
    }
    __syncthreads();   // staging reads complete before WB fill

    // WB rows: [Wih2 cols 0-51 | Whh2 cols 56-107], zeros at 50-55 & 106-107
    for (int i = tid; i < 200 * WB_STR; i += NTH) {
        int r = i / WB_STR, c = i % WB_STR;
        float v = 0.f;
        if (c < 52)      { if (c < HIDN) v = Wih2[r * HIDN + c]; }
        else if (c >= 56){ int cc = c - 56; if (cc < HIDN) v = Whh2[r * HIDN + cc]; }
        sm[WB_OFF + i] = v;
    }
    // WC rows (150: i, g, o): src row = rr + (rr<50 ? 0 : 50)
    for (int i = tid; i < 150 * WB_STR; i += NTH) {
        int rr = i / WB_STR, c = i % WB_STR;
        int src = rr + ((rr < 50) ? 0 : 50);
        float v = 0.f;
        if (c < 52)      { if (c < HIDN) v = Wih3[src * HIDN + c]; }
        else if (c >= 56){ int cc = c - 56; if (cc < HIDN) v = Whh3[src * HIDN + cc]; }
        sm[WC_OFF + i] = v;
    }
    for (int i = tid; i < OUT_D * HIDN; i += NTH) sm[W2_OFF + i] = W2[i];

    // zero all state buffers (incl. pad cols; never overwritten)
    for (int i = XH1_OFF + tid; i < SMEM_FLT; i += NTH) sm[i] = 0.f;
    __syncthreads();
    // x(0) into XH1 parity 1 x-part
    if (tid < NB * IN_D) {
        int b = tid / IN_D, k = tid % IN_D;
        sm[XH1_OFF + 320 + (k >> 1) * 8 + 2 * b + (k & 1)] =
            x[((size_t)(b0 + b) * T_LEN) * IN_D + k];
    }
    __syncthreads();

    // ---------------- role setup ----------------
    const int lane = tid & 31, wrp = tid >> 5;
    const bool ishelp = (wrp == 13);
    const int qd = lane >> 3;                   // column quarter (bits 3,4)
    const int bp = (lane >> 2) & 1;             // batch pair (bit 2)
    const int u_raw = wrp * 4 + (lane & 3);     // 0..51 for gate warps
    const int u = (u_raw < HIDN) ? u_raw : (HIDN - 1);
    const bool dostore = (!ishelp) && (u_raw < HIDN) && (qd == 0);
    const int ob = lane >> 3, oo = lane & 7;    // helper mapping

    // weight pointers: u-stride 76/108 (phase-conflict-free), quarter offsets 20/28 cols
    const float* wa_i = sm + WA_OFF + u * WA_STR + qd * 20;
    const float* wa_f = wa_i + 50 * WA_STR;
    const float* wa_g = wa_i + 100 * WA_STR;
    const float* wa_o = wa_i + 150 * WA_STR;
    const float* wb_i = sm + WB_OFF + u * WB_STR + qd * 28;
    const float* wb_f = wb_i + 50 * WB_STR;
    const float* wb_g = wb_i + 100 * WB_STR;
    const float* wb_o = wb_i + 150 * WB_STR;
    const float* wc_i = sm + WC_OFF + u * WB_STR + qd * 28;
    const float* wc_g = wc_i + 50 * WB_STR;
    const float* wc_o = wc_i + 100 * WB_STR;

    float bai = 0, baf = 0, bag = 0, bao = 0;
    float bbi = 0, bbf = 0, bbg = 0, bbo = 0;
    float bci = 0, bcg = 0, bco = 0, b2r = 0;
    if (!ishelp) {
        bai = bih1[u] + bhh1[u];
        baf = bih1[u + 50] + bhh1[u + 50];
        bag = bih1[u + 100] + bhh1[u + 100];
        bao = bih1[u + 150] + bhh1[u + 150];
        for (int j = 0; j < HIDN; j++) {
            float bj = b1[j];
            bai += Wih1[u * HIDN + j] * bj;
            baf += Wih1[(u + 50) * HIDN + j] * bj;
            bag += Wih1[(u + 100) * HIDN + j] * bj;
            bao += Wih1[(u + 150) * HIDN + j] * bj;
        }
        bbi = bih2[u] + bhh2[u];
        bbf = bih2[u + 50] + bhh2[u + 50];
        bbg = bih2[u + 100] + bhh2[u + 100];
        bbo = bih2[u + 150] + bhh2[u + 150];
        bci = bih3[u] + bhh3[u];
        bcg = bih3[u + 100] + bhh3[u + 100];
        bco = bih3[u + 150] + bhh3[u + 150];
    } else {
        b2r = b2[oo];
    }

    const int up8 = (u >> 1) * 8 + (u & 1);
    // input quarter offsets (floats): cell1 qd*80 (20 cols), cells2/3 qd*112 (28 cols)
    const int q1off = qd * 80 + 4 * bp;
    const int q2off = qd * 112 + 4 * bp;
    float c1s[2] = {0.f, 0.f};
    float czs[2] = {0.f, 0.f};
    float lo, hi;
    float xv0 = 0.f, xv1 = 0.f, xv2 = 0.f;   // helper's in-flight x values

    // ---------------- prologue: cell1(0) || helper loads x(1) ----------------
    if (!ishelp) {
        Acc8 A{};
        gemv_q<5, true>(wa_i, wa_f, wa_g, wa_o, sm + XH1_OFF + 320 + q1off, A);
        CMB4(A)
#pragma unroll
        for (int k = 0; k < 2; k++) {
            ull Ai = k ? A.i1 : A.i0, Af = k ? A.f1 : A.f0;
            ull Ag = k ? A.g1 : A.g0, Ao = k ? A.o1 : A.o0;
            upk(Ai, lo, hi); float iv = sigm(lo + hi + bai);
            upk(Af, lo, hi); float fv = sigm(lo + hi + baf);
            upk(Ag, lo, hi); float gv = tanhap(lo + hi + bag);
            upk(Ao, lo, hi); float ov = sigm(lo + hi + bao);
            c1s[k] = fv * c1s[k] + iv * gv;
            float h = ov * tanhap(c1s[k]);
            if (dostore) {
                int b = 2 * bp + k;
                sm[XH1_OFF + 80 + up8 + 2 * b] = h;     // XH1[0].h1
                sm[C2_OFF + up8 + 2 * b] = h;           // C2 slot h1[0]
            }
        }
    } else {
        { int e = lane;      int b = e / IN_D, k = e % IN_D;
          xv0 = x[((size_t)(b0 + b) * T_LEN + 1) * IN_D + k]; }
        { int e = lane + 32; int b = e / IN_D, k = e % IN_D;
          xv1 = x[((size_t)(b0 + b) * T_LEN + 1) * IN_D + k]; }
        if (lane + 64 < NB * IN_D) {
          int e = lane + 64; int b = e / IN_D, k = e % IN_D;
          xv2 = x[((size_t)(b0 + b) * T_LEN + 1) * IN_D + k]; }
    }
    __syncthreads();

    // ---------------- main loop: 2 barriers/step ----------------
    for (int t = 0; t < T_LEN; t++) {
        const int q = t & 1;

        // ---- phase alpha: cell2(t) || helper {store x(t+1), out(t-1)} ----
        if (!ishelp) {
            Acc8 A{};
            gemv_q<7, true>(wb_i, wb_f, wb_g, wb_o,
                            sm + C2_OFF + q * 448 + q2off, A);
            CMB4(A)
#pragma unroll
            for (int k = 0; k < 2; k++) {
                ull Ai = k ? A.i1 : A.i0, Af = k ? A.f1 : A.f0;
                ull Ag = k ? A.g1 : A.g0, Ao = k ? A.o1 : A.o0;
                upk(Ai, lo, hi); float iv = sigm(lo + hi + bbi);
                upk(Af, lo, hi); float fv = sigm(lo + hi + bbf);
                upk(Ag, lo, hi); float gv = tanhap(lo + hi + bbg);
                upk(Ao, lo, hi); float ov = sigm(lo + hi + bbo);
                float c2t = fv * czs[k] + iv * gv;
                float h = ov * tanhap(c2t);
                if (dostore) {
                    int b = 2 * bp + k;
                    sm[C2_OFF + 224 + (1 - q) * 448 + up8 + 2 * b] = h;  // h2a[q]
                    sm[C3_OFF + q * 448 + up8 + 2 * b] = h;              // h2b[q]
                }
            }
        } else {
            if (t + 1 < T_LEN) {   // store x(t+1) -> XH1[q].x (read in beta(t))
                { int e = lane;      int b = e / IN_D, k = e % IN_D;
                  sm[XH1_OFF + q * 320 + (k >> 1) * 8 + 2 * b + (k & 1)] = xv0; }
                { int e = lane + 32; int b = e / IN_D, k = e % IN_D;
                  sm[XH1_OFF + q * 320 + (k >> 1) * 8 + 2 * b + (k & 1)] = xv1; }
                if (lane + 64 < NB * IN_D) {
                  int e = lane + 64; int b = e / IN_D, k = e % IN_D;
                  sm[XH1_OFF + q * 320 + (k >> 1) * 8 + 2 * b + (k & 1)] = xv2; }
            }
            if (t > 0) {   // out(t-1): h3(t-1) at C3 + 224 + q*448
                const float* h3p = sm + C3_OFF + 224 + q * 448;
                float acc = b2r;
#pragma unroll
                for (int j = 0; j < HIDN; j++)
                    acc += sm[W2_OFF + oo * HIDN + j] *
                           h3p[(j >> 1) * 8 + 2 * ob + (j & 1)];
                out[((size_t)(b0 + ob) * T_LEN + (t - 1)) * OUT_D + oo] = acc;
            }
        }
        __syncthreads();

        // ---- phase beta: cell3(t) + cell1(t+1) || helper loads x(t+2) ----
        if (!ishelp) {
            Acc8 A3{};
            gemv_q<7, false>(wc_i, wc_i, wc_g, wc_o,
                             sm + C3_OFF + q * 448 + q2off, A3);
            if (t + 1 < T_LEN) {
                Acc8 A1{};
                gemv_q<5, true>(wa_i, wa_f, wa_g, wa_o,
                                sm + XH1_OFF + q * 320 + q1off, A1);
                CMB3(A3)
#pragma unroll
                for (int k = 0; k < 2; k++) {
                    ull Ai = k ? A3.i1 : A3.i0;
                    ull Ag = k ? A3.g1 : A3.g0, Ao = k ? A3.o1 : A3.o0;
                    upk(Ai, lo, hi); float iv = sigm(lo + hi + bci);
                    upk(Ag, lo, hi); float gv = tanhap(lo + hi + bcg);
                    upk(Ao, lo, hi); float ov = sigm(lo + hi + bco);
                    czs[k] = iv * gv;
                    float h = ov * tanhap(czs[k]);
                    if (dostore)
                        sm[C3_OFF + 224 + (1 - q) * 448 + up8 + 2 * (2 * bp + k)] = h;
                }
                CMB4(A1)
#pragma unroll
                for (int k = 0; k < 2; k++) {
                    ull Ai = k ? A1.i1 : A1.i0, Af = k ? A1.f1 : A1.f0;
                    ull Ag = k ? A1.g1 : A1.g0, Ao = k ? A1.o1 : A1.o0;
                    upk(Ai, lo, hi); float iv = sigm(lo + hi + bai);
                    upk(Af, lo, hi); float fv = sigm(lo + hi + baf);
                    upk(Ag, lo, hi); float gv = tanhap(lo + hi + bag);
                    upk(Ao, lo, hi); float ov = sigm(lo + hi + bao);
                    c1s[k] = fv * c1s[k] + iv * gv;
                    float h = ov * tanhap(c1s[k]);
                    if (dostore) {
                        int b = 2 * bp + k;
                        sm[XH1_OFF + (1 - q) * 320 + 80 + up8 + 2 * b] = h;
                        sm[C2_OFF + (1 - q) * 448 + up8 + 2 * b] = h;
                    }
                }
            } else {
                CMB3(A3)
#pragma unroll
                for (int k = 0; k < 2; k++) {
                    ull Ai = k ? A3.i1 : A3.i0;
                    ull Ag = k ? A3.g1 : A3.g0, Ao = k ? A3.o1 : A3.o0;
                    upk(Ai, lo, hi); float iv = sigm(lo + hi + bci);
                    upk(Ag, lo, hi); float gv = tanhap(lo + hi + bcg);
                    upk(Ao, lo, hi); float ov = sigm(lo + hi + bco);
                    czs[k] = iv * gv;
                    float h = ov * tanhap(czs[k]);
                    if (dostore)
                        sm[C3_OFF + 224 + (1 - q) * 448 + up8 + 2 * (2 * bp + k)] = h;
                }
            }
        } else {
            if (t + 2 < T_LEN) {   // load x(t+2); stored in alpha(t+1)
                { int e = lane;      int b = e / IN_D, k = e % IN_D;
                  xv0 = x[((size_t)(b0 + b) * T_LEN + t + 2) * IN_D + k]; }
                { int e = lane + 32; int b = e / IN_D, k = e % IN_D;
                  xv1 = x[((size_t)(b0 + b) * T_LEN + t + 2) * IN_D + k]; }
                if (lane + 64 < NB * IN_D) {
                  int e = lane + 64; int b = e / IN_D, k = e % IN_D;
                  xv2 = x[((size_t)(b0 + b) * T_LEN + t + 2) * IN_D + k]; }
            }
        }
        __syncthreads();
    }

    // epilogue: out(T_LEN-1); h3(T-1) (parity 1) at C3 + 224
    if (ishelp) {
        const float* h3p = sm + C3_OFF + 224;
        float acc = b2r;
#pragma unroll
        for (int j = 0; j < HIDN; j++)
            acc += sm[W2_OFF + oo * HIDN + j] *
                   h3p[(j >> 1) * 8 + 2 * ob + (j & 1)];
        out[((size_t)(b0 + ob) * T_LEN + (T_LEN - 1)) * OUT_D + oo] = acc;
    }
}

extern "C" void kernel_launch(void* const* d_in, const int* in_sizes, int n_in,
                              void* d_out, int out_size)
{
    const float* x    = (const float*)d_in[0];
    const float* W1   = (const float*)d_in[1];
    const float* b1   = (const float*)d_in[2];
    const float* Wih1 = (const float*)d_in[3];
    const float* Whh1 = (const float*)d_in[4];
    const float* bih1 = (const float*)d_in[5];
    const float* bhh1 = (const float*)d_in[6];
    const float* Wih2 = (const float*)d_in[7];
    const float* Whh2 = (const float*)d_in[8];
    const float* bih2 = (const float*)d_in[9];
    const float* bhh2 = (const float*)d_in[10];
    const float* Wih3 = (const float*)d_in[11];
    const float* Whh3 = (const float*)d_in[12];
    const float* bih3 = (const float*)d_in[13];
    const float* bhh3 = (const float*)d_in[14];
    const float* W2   = (const float*)d_in[15];
    const float* b2   = (const float*)d_in[16];
    float* out = (float*)d_out;

    const int smem_bytes = SMEM_FLT * sizeof(float);  // 223,328
    cudaFuncSetAttribute(lstm_persist_kernel,
                         cudaFuncAttributeMaxDynamicSharedMemorySize, smem_bytes);

    lstm_persist_kernel<<<NCTA, NTH, smem_bytes>>>(
        x, W1, b1, Wih1, Whh1, bih1, bhh1,
        Wih2, Whh2, bih2, bhh2, Wih3, Whh3, bih3, bhh3,
        W2, b2, out);
}